// round 13
// baseline (speedup 1.0000x reference)
#include <cuda_runtime.h>
#include <math.h>

#define N_BINS 1024
#define N_COPIES 8           // one PRIVATE smem histogram per warp (256 thr / 32)
#define HIST_BLOCKS 592      // 4 * 148 SMs — R3 optimum (32 warps/SM)
#define HIST_THREADS 256

__device__ unsigned int g_counts[N_BINS];     // zero at load; reset each run below
__device__ unsigned int g_done;               // arrival counter, reset each run

__global__ void __launch_bounds__(HIST_THREADS) hist_kernel(
    const int* __restrict__ idx, long long n, float inv_n,
    float* __restrict__ out)
{
    __shared__ __align__(16) unsigned int sh[N_COPIES][N_BINS];
    __shared__ bool s_last;
    __shared__ float red[HIST_THREADS / 32];

    unsigned int* flat = &sh[0][0];
    for (int i = threadIdx.x; i < N_COPIES * N_BINS; i += blockDim.x)
        flat[i] = 0u;
    __syncthreads();

    unsigned int* h = sh[threadIdx.x >> 5];   // fully private per-warp copy

    long long tid    = (long long)blockIdx.x * blockDim.x + threadIdx.x;
    long long stride = (long long)gridDim.x * blockDim.x;
    long long n4     = n >> 2;
    const int4* p4   = (const int4*)idx;

    // main loop: 2 outstanding int4 loads per iteration (R3's exact body)
    long long i = tid;
    for (; i + stride < n4; i += 2 * stride) {
        int4 a = p4[i];
        int4 b = p4[i + stride];
        atomicAdd(&h[a.x & (N_BINS - 1)], 1u);
        atomicAdd(&h[a.y & (N_BINS - 1)], 1u);
        atomicAdd(&h[a.z & (N_BINS - 1)], 1u);
        atomicAdd(&h[a.w & (N_BINS - 1)], 1u);
        atomicAdd(&h[b.x & (N_BINS - 1)], 1u);
        atomicAdd(&h[b.y & (N_BINS - 1)], 1u);
        atomicAdd(&h[b.z & (N_BINS - 1)], 1u);
        atomicAdd(&h[b.w & (N_BINS - 1)], 1u);
    }
    for (; i < n4; i += stride) {
        int4 a = p4[i];
        atomicAdd(&h[a.x & (N_BINS - 1)], 1u);
        atomicAdd(&h[a.y & (N_BINS - 1)], 1u);
        atomicAdd(&h[a.z & (N_BINS - 1)], 1u);
        atomicAdd(&h[a.w & (N_BINS - 1)], 1u);
    }
    // remainder (n not multiple of 4)
    for (long long r = (n4 << 2) + tid; r < n; r += stride)
        atomicAdd(&h[idx[r] & (N_BINS - 1)], 1u);

    __syncthreads();

    // flush: 4 bins per thread-iteration via LDS.128 over the 8 copies,
    // then 4 REDG — same atomic count/addresses as R3, 4x fewer LDS.
    for (int b = threadIdx.x * 4; b < N_BINS; b += blockDim.x * 4) {
        uint4 s = make_uint4(0u, 0u, 0u, 0u);
        #pragma unroll
        for (int c = 0; c < N_COPIES; c++) {
            uint4 q = *(const uint4*)&sh[c][b];
            s.x += q.x; s.y += q.y; s.z += q.z; s.w += q.w;
        }
        atomicAdd(&g_counts[b + 0], s.x);
        atomicAdd(&g_counts[b + 1], s.y);
        atomicAdd(&g_counts[b + 2], s.z);
        atomicAdd(&g_counts[b + 3], s.w);
    }

    // last-block-done: fused finalize
    __threadfence();
    if (threadIdx.x == 0)
        s_last = (atomicAdd(&g_done, 1u) == (unsigned)(gridDim.x - 1));
    __syncthreads();

    if (s_last) {
        int t = threadIdx.x;
        // 1024 bins / 256 threads = 4 bins per thread, one uint4 each
        uint4 c = ((const uint4*)g_counts)[t];
        ((uint4*)g_counts)[t] = make_uint4(0u, 0u, 0u, 0u);  // reset for next replay
        float p0 = (float)c.x * inv_n;
        float p1 = (float)c.y * inv_n;
        float p2 = (float)c.z * inv_n;
        float p3 = (float)c.w * inv_n;
        float v = p0 * __logf(p0 + 1e-8f)
                + p1 * __logf(p1 + 1e-8f)
                + p2 * __logf(p2 + 1e-8f)
                + p3 * __logf(p3 + 1e-8f);

        #pragma unroll
        for (int o = 16; o > 0; o >>= 1) v += __shfl_down_sync(0xFFFFFFFFu, v, o);
        if ((t & 31) == 0) red[t >> 5] = v;
        __syncthreads();
        if (t < 32) {
            float s = (t < HIST_THREADS / 32) ? red[t] : 0.0f;
            #pragma unroll
            for (int o = 4; o > 0; o >>= 1) s += __shfl_down_sync(0xFFFFFFFFu, s, o);
            if (t == 0) {
                out[0] = __expf(-s);
                g_done = 0u;                  // reset arrival counter for next replay
            }
        }
    }
}

extern "C" void kernel_launch(void* const* d_in, const int* in_sizes, int n_in,
                              void* d_out, int out_size) {
    const int* idx = (const int*)d_in[0];
    long long n    = (long long)in_sizes[0];
    float* out     = (float*)d_out;

    hist_kernel<<<HIST_BLOCKS, HIST_THREADS>>>(idx, n, 1.0f / (float)n, out);
}

// round 14
// speedup vs baseline: 1.8784x; 1.8784x over previous
#include <cuda_runtime.h>
#include <math.h>

#define N_BINS 1024
#define N_COPIES 8           // one PRIVATE smem histogram per warp (256 thr / 32)
#define HIST_BLOCKS 592      // 4 * 148 SMs — R3 optimum (32 warps/SM)
#define HIST_THREADS 256

__device__ unsigned int g_counts[N_BINS];     // zero at load; reset each run below
__device__ unsigned int g_done;               // arrival counter, reset each run

__global__ void __launch_bounds__(HIST_THREADS) hist_kernel(
    const int* __restrict__ idx, long long n, float inv_n,
    float* __restrict__ out)
{
    __shared__ unsigned int sh[N_COPIES][N_BINS];
    __shared__ bool s_last;
    __shared__ float red[HIST_THREADS / 32];

    unsigned int* flat = &sh[0][0];
    for (int i = threadIdx.x; i < N_COPIES * N_BINS; i += blockDim.x)
        flat[i] = 0u;
    __syncthreads();

    unsigned int* h = sh[threadIdx.x >> 5];   // fully private per-warp copy

    long long tid    = (long long)blockIdx.x * blockDim.x + threadIdx.x;
    long long stride = (long long)gridDim.x * blockDim.x;
    long long n4     = n >> 2;
    const int4* p4   = (const int4*)idx;

    // main loop: 2 outstanding int4 loads per iteration (R3's exact body)
    long long i = tid;
    for (; i + stride < n4; i += 2 * stride) {
        int4 a = p4[i];
        int4 b = p4[i + stride];
        atomicAdd(&h[a.x & (N_BINS - 1)], 1u);
        atomicAdd(&h[a.y & (N_BINS - 1)], 1u);
        atomicAdd(&h[a.z & (N_BINS - 1)], 1u);
        atomicAdd(&h[a.w & (N_BINS - 1)], 1u);
        atomicAdd(&h[b.x & (N_BINS - 1)], 1u);
        atomicAdd(&h[b.y & (N_BINS - 1)], 1u);
        atomicAdd(&h[b.z & (N_BINS - 1)], 1u);
        atomicAdd(&h[b.w & (N_BINS - 1)], 1u);
    }
    for (; i < n4; i += stride) {
        int4 a = p4[i];
        atomicAdd(&h[a.x & (N_BINS - 1)], 1u);
        atomicAdd(&h[a.y & (N_BINS - 1)], 1u);
        atomicAdd(&h[a.z & (N_BINS - 1)], 1u);
        atomicAdd(&h[a.w & (N_BINS - 1)], 1u);
    }
    // remainder (n not multiple of 4)
    for (long long r = (n4 << 2) + tid; r < n; r += stride)
        atomicAdd(&h[idx[r] & (N_BINS - 1)], 1u);

    __syncthreads();

    // flush per-warp copies -> global histogram (R3's exact form)
    for (int b = threadIdx.x; b < N_BINS; b += blockDim.x) {
        unsigned int s = 0;
        #pragma unroll
        for (int c = 0; c < N_COPIES; c++) s += sh[c][b];
        atomicAdd(&g_counts[b], s);
    }

    // last-block-done: fused finalize
    __threadfence();
    if (threadIdx.x == 0)
        s_last = (atomicAdd(&g_done, 1u) == (unsigned)(gridDim.x - 1));
    __syncthreads();

    if (s_last) {
        int t = threadIdx.x;
        volatile unsigned int* gc = g_counts;
        float v = 0.0f;
        #pragma unroll
        for (int k = 0; k < N_BINS / HIST_THREADS; k++) {
            int b = t + k * HIST_THREADS;
            unsigned int c = gc[b];
            g_counts[b] = 0u;                 // reset for next replay
            float p = (float)c * inv_n;
            v += p * __logf(p + 1e-8f);       // MUFU fast path (only change vs R3)
        }
        #pragma unroll
        for (int o = 16; o > 0; o >>= 1) v += __shfl_down_sync(0xFFFFFFFFu, v, o);
        if ((t & 31) == 0) red[t >> 5] = v;
        __syncthreads();
        if (t < 32) {
            float s = (t < HIST_THREADS / 32) ? red[t] : 0.0f;
            #pragma unroll
            for (int o = 4; o > 0; o >>= 1) s += __shfl_down_sync(0xFFFFFFFFu, s, o);
            if (t == 0) {
                out[0] = __expf(-s);
                g_done = 0u;                  // reset arrival counter for next replay
            }
        }
    }
}

extern "C" void kernel_launch(void* const* d_in, const int* in_sizes, int n_in,
                              void* d_out, int out_size) {
    const int* idx = (const int*)d_in[0];
    long long n    = (long long)in_sizes[0];
    float* out     = (float*)d_out;

    hist_kernel<<<HIST_BLOCKS, HIST_THREADS>>>(idx, n, 1.0f / (float)n, out);
}

// round 15
// speedup vs baseline: 2.0981x; 1.1170x over previous
#include <cuda_runtime.h>
#include <math.h>

#define N_BINS 1024
#define N_COPIES 8           // one PRIVATE smem histogram per warp (256 thr / 32)
#define HIST_BLOCKS 592      // 4 * 148 SMs — R3 optimum (32 warps/SM)
#define HIST_THREADS 256

__device__ unsigned int g_counts[N_BINS];     // zero at load; reset each run below
__device__ unsigned int g_done;               // arrival counter, reset each run

__global__ void __launch_bounds__(HIST_THREADS) hist_kernel(
    const int* __restrict__ idx, long long n, float inv_n,
    float* __restrict__ out)
{
    __shared__ unsigned int sh[N_COPIES][N_BINS];
    __shared__ bool s_last;
    __shared__ float red[HIST_THREADS / 32];

    unsigned int* flat = &sh[0][0];
    for (int i = threadIdx.x; i < N_COPIES * N_BINS; i += blockDim.x)
        flat[i] = 0u;
    __syncthreads();

    unsigned int* h = sh[threadIdx.x >> 5];   // fully private per-warp copy

    long long tid    = (long long)blockIdx.x * blockDim.x + threadIdx.x;
    long long stride = (long long)gridDim.x * blockDim.x;
    long long n4     = n >> 2;
    const int4* p4   = (const int4*)idx;

    // Indices are randint(0, 1024) by problem construction: no mask needed.
    // Mainloop: 2 outstanding int4 loads per iteration (R3's memory-op mix,
    // minus 4 redundant LOP3s per int4).
    long long i = tid;
    for (; i + stride < n4; i += 2 * stride) {
        int4 a = p4[i];
        int4 b = p4[i + stride];
        atomicAdd(&h[a.x], 1u);
        atomicAdd(&h[a.y], 1u);
        atomicAdd(&h[a.z], 1u);
        atomicAdd(&h[a.w], 1u);
        atomicAdd(&h[b.x], 1u);
        atomicAdd(&h[b.y], 1u);
        atomicAdd(&h[b.z], 1u);
        atomicAdd(&h[b.w], 1u);
    }
    for (; i < n4; i += stride) {
        int4 a = p4[i];
        atomicAdd(&h[a.x], 1u);
        atomicAdd(&h[a.y], 1u);
        atomicAdd(&h[a.z], 1u);
        atomicAdd(&h[a.w], 1u);
    }
    // remainder (n not multiple of 4)
    for (long long r = (n4 << 2) + tid; r < n; r += stride)
        atomicAdd(&h[idx[r]], 1u);

    __syncthreads();

    // flush per-warp copies -> global histogram (R3's exact form)
    for (int b = threadIdx.x; b < N_BINS; b += blockDim.x) {
        unsigned int s = 0;
        #pragma unroll
        for (int c = 0; c < N_COPIES; c++) s += sh[c][b];
        atomicAdd(&g_counts[b], s);
    }

    // last-block-done: fused finalize (R3's exact form)
    __threadfence();
    if (threadIdx.x == 0)
        s_last = (atomicAdd(&g_done, 1u) == (unsigned)(gridDim.x - 1));
    __syncthreads();

    if (s_last) {
        int t = threadIdx.x;
        volatile unsigned int* gc = g_counts;
        float v = 0.0f;
        #pragma unroll
        for (int k = 0; k < N_BINS / HIST_THREADS; k++) {
            int b = t + k * HIST_THREADS;
            unsigned int c = gc[b];
            g_counts[b] = 0u;                 // reset for next replay
            float p = (float)c * inv_n;
            v += p * logf(p + 1e-8f);
        }
        #pragma unroll
        for (int o = 16; o > 0; o >>= 1) v += __shfl_down_sync(0xFFFFFFFFu, v, o);
        if ((t & 31) == 0) red[t >> 5] = v;
        __syncthreads();
        if (t < 32) {
            float s = (t < HIST_THREADS / 32) ? red[t] : 0.0f;
            #pragma unroll
            for (int o = 4; o > 0; o >>= 1) s += __shfl_down_sync(0xFFFFFFFFu, s, o);
            if (t == 0) {
                out[0] = expf(-s);
                g_done = 0u;                  // reset arrival counter for next replay
            }
        }
    }
}

extern "C" void kernel_launch(void* const* d_in, const int* in_sizes, int n_in,
                              void* d_out, int out_size) {
    const int* idx = (const int*)d_in[0];
    long long n    = (long long)in_sizes[0];
    float* out     = (float*)d_out;

    hist_kernel<<<HIST_BLOCKS, HIST_THREADS>>>(idx, n, 1.0f / (float)n, out);
}